// round 14
// baseline (speedup 1.0000x reference)
#include <cuda_runtime.h>
#include <cuda_fp16.h>
#include <math.h>
#include <stdint.h>

// ---------------- problem constants ----------------
#define M_TOT   12288
#define K1      768
#define H_DIM   3072
#define N_SHARED 512
#define N_PART  256
#define D_OUT   768
#define S_LEN   192
#define B_TOT   64

#define N_X   ((size_t)M_TOT * K1)
#define N_W1  ((size_t)H_DIM * K1)
#define N_W2  ((size_t)N_SHARED * H_DIM)
#define N_EW  ((size_t)6 * N_PART * H_DIM)

// ---------------- tiling ----------------
#define BK 64
#define ROWB 144u
#define TILE_B (128u * ROWB)
#define STAGE_B (2u * TILE_B)
#define SMEM_BYTES (3 * 36864)

#define PREPB_CTAS 74
#define FC1_CTAS   (2304 + PREPB_CTAS)   // 2378
#define FC2_CTAS   640
#define N_BANDS    96                    // 128-row bands of g_h

// ---------------- device scratch ----------------
static __device__ __half g_h [(size_t)M_TOT * H_DIM];
static __device__ __half g_x [N_X];
static __device__ __half g_w1[N_W1];
static __device__ __half g_w2[N_W2];
static __device__ __half g_ew[N_EW];
static __device__ int    g_idx[B_TOT];
static __device__ int    g_done[N_BANDS];   // fc1 n-tiles completed per band (target 24)
static __device__ int    g_wdone;           // prep-B CTAs completed (target 74)

// ---------------- helpers ----------------
__device__ __forceinline__ float gelu_erf(float x) {
    return 0.5f * x * (1.0f + erff(x * 0.70710678118654752440f));
}
__device__ __forceinline__ uint32_t smem_u32(const void* p) {
    uint32_t a;
    asm("{ .reg .u64 t; cvta.to.shared.u64 t, %1; cvt.u32.u64 %0, t; }" : "=r"(a) : "l"(p));
    return a;
}
__device__ __forceinline__ void cp16(uint32_t dst, const __half* src) {
    asm volatile("cp.async.cg.shared.global [%0], [%1], 16;" :: "r"(dst), "l"(src));
}
__device__ __forceinline__ void cp_commit() {
    asm volatile("cp.async.commit_group;" ::: "memory");
}
__device__ __forceinline__ void ldsm4(uint32_t* r, uint32_t addr) {
    asm volatile("ldmatrix.sync.aligned.m8n8.x4.shared.b16 {%0,%1,%2,%3}, [%4];"
                 : "=r"(r[0]), "=r"(r[1]), "=r"(r[2]), "=r"(r[3]) : "r"(addr));
}
__device__ __forceinline__ void mma_f16(float* c, const uint32_t* a, uint32_t b0, uint32_t b1) {
    asm volatile(
        "mma.sync.aligned.m16n8k16.row.col.f32.f16.f16.f32 "
        "{%0,%1,%2,%3}, {%4,%5,%6,%7}, {%8,%9}, {%0,%1,%2,%3};"
        : "+f"(c[0]), "+f"(c[1]), "+f"(c[2]), "+f"(c[3])
        : "r"(a[0]), "r"(a[1]), "r"(a[2]), "r"(a[3]), "r"(b0), "r"(b1));
}
__device__ __forceinline__ void spin_until(volatile int* p, int target) {
    while (*p < target) { __nanosleep(128); }
}

// ---------------- prep: fp32 -> fp16 for X + w1, decode indices, zero counters ----
__global__ void prep_kernel(const float* __restrict__ X,
                            const float* __restrict__ w1,
                            const int*   __restrict__ raw)
{
    if (blockIdx.x == 0) {
        if (threadIdx.x == 0) {
            int odd_or = 0;
            for (int i = 1; i < B_TOT; i += 2) odd_or |= raw[i];
            const int is64 = (odd_or == 0);
            for (int b = 0; b < B_TOT; b++) g_idx[b] = is64 ? raw[2 * b] : raw[b];
            g_wdone = 0;
        }
        if (threadIdx.x < N_BANDS) g_done[threadIdx.x] = 0;
    }
    const size_t total4 = (N_X + N_W1) / 4;
    const size_t b1 = N_X / 4;
    const size_t stride = (size_t)gridDim.x * blockDim.x;

    auto body = [&](size_t i) {
        const float4* src; __half2* dst; size_t o;
        if (i < b1) { src = (const float4*)X;  dst = (__half2*)g_x;  o = i; }
        else        { src = (const float4*)w1; dst = (__half2*)g_w1; o = i - b1; }
        float4 v = src[o];
        dst[2 * o]     = __floats2half2_rn(v.x, v.y);
        dst[2 * o + 1] = __floats2half2_rn(v.z, v.w);
    };

    size_t i = (size_t)blockIdx.x * blockDim.x + threadIdx.x;
    for (; i + stride < total4; i += 2 * stride) {
        body(i);
        body(i + stride);
    }
    if (i < total4) body(i);
}

// ---------------- fused GEMM kernel ----------------
// blockIdx < 2378: fc1 (2304 GEMM CTAs + 74 scattered prep-B CTAs converting w2/ew).
//   fc1 GEMM CTA signals g_done[band] (24 per 128-row band) after writing g_h.
// blockIdx >= 2378: fc2 (384 shared M=128 + 256 expert M=96 jobs); each CTA
//   spin-waits (volatile+nanosleep) for its band(s) + w-conversion before loading.
//   Deadlock-free: CTAs dispatch in blockIdx order; fc1 CTAs never wait.
__global__ void __launch_bounds__(256, 2) moe_kernel(
    const float* __restrict__ fc1_b,
    const float* __restrict__ w2,
    const float* __restrict__ ew,
    const float* __restrict__ fc2_b,
    const float* __restrict__ eb,
    float* __restrict__ out)
{
    extern __shared__ char smch[];
    const uint32_t sb = smem_u32(smch);
    const int tid  = threadIdx.x;
    const int lane = tid & 31;
    const int wid  = tid >> 5;
    const int g = lane >> 2;
    const int t = lane & 3;

    const int b = blockIdx.x;

    if (b < FC1_CTAS) {
        // ================= fc1 side =================
        const int q = b >> 5;
        if ((b & 31) == 31 && q < PREPB_CTAS) {
            // prep-B: convert w2 + ew to fp16
            const size_t nw2 = N_W2 / 4;
            const size_t tot = (N_W2 + N_EW) / 4;
            const size_t stride = (size_t)PREPB_CTAS * 256;
            for (size_t i = (size_t)q * 256 + tid; i < tot; i += stride) {
                const float4* src; __half2* dst; size_t o;
                if (i < nw2) { src = (const float4*)w2; dst = (__half2*)g_w2; o = i; }
                else         { src = (const float4*)ew; dst = (__half2*)g_ew; o = i - nw2; }
                float4 v = src[o];
                dst[2 * o]     = __floats2half2_rn(v.x, v.y);
                dst[2 * o + 1] = __floats2half2_rn(v.z, v.w);
            }
            __threadfence();
            __syncthreads();
            if (tid == 0) atomicAdd(&g_wdone, 1);
            return;
        }

        const int gj = b - ((q < PREPB_CTAS) ? q : PREPB_CTAS);
        const int bm = (gj / 24) * 128;
        const int bn = (gj % 24) * 128;

        const __half* A = g_x + (size_t)bm * K1;
        const __half* B = g_w1 + (size_t)bn * K1;
        __half* outp = g_h + (size_t)bm * H_DIM + bn;
        const float* bp = fc1_b + bn;
        const int NS = K1 / BK;

        const int wm = (wid & 3) * 32;
        const int wn = (wid >> 2) * 64;

        float acc[2][8][4];
#pragma unroll
        for (int mt = 0; mt < 2; mt++)
#pragma unroll
            for (int nt = 0; nt < 8; nt++)
#pragma unroll
                for (int qd = 0; qd < 4; qd++) acc[mt][nt][qd] = 0.f;

        const int r0 = tid >> 3;
        const int c4 = tid & 7;
        const __half* Ag = A + (size_t)r0 * K1 + c4 * 8;
        const __half* Bg = B + (size_t)r0 * K1 + c4 * 8;
        const uint32_t sa0 = sb + (uint32_t)r0 * ROWB + (uint32_t)c4 * 16u;
        const uint32_t sb0 = sa0 + TILE_B;

        const int arow = (lane & 7) + ((lane >> 3) & 1) * 8;
        const int akh  = (lane >> 4);
        uint32_t aoff[2], boff[4];
#pragma unroll
        for (int mt = 0; mt < 2; mt++)
            aoff[mt] = (uint32_t)(wm + mt * 16 + arow) * ROWB + (uint32_t)akh * 16u;
        const int brow = (lane & 7) + ((lane >> 4) & 1) * 8;
        const int bkh  = (lane >> 3) & 1;
#pragma unroll
        for (int nb = 0; nb < 4; nb++)
            boff[nb] = (uint32_t)(wn + nb * 16 + brow) * ROWB + (uint32_t)bkh * 16u;

#pragma unroll
        for (int s = 0; s < 2; s++) {
            const int k0 = s * BK;
            const uint32_t so = (uint32_t)s * STAGE_B;
#pragma unroll
            for (int i = 0; i < 4; i++) {
                cp16(sa0 + so + (uint32_t)i * 32u * ROWB, Ag + (size_t)(i * 32) * K1 + k0);
                cp16(sb0 + so + (uint32_t)i * 32u * ROWB, Bg + (size_t)(i * 32) * K1 + k0);
            }
            cp_commit();
        }

        int st = 0;
        for (int s = 0; s < NS; s++) {
            if (s < NS - 1) asm volatile("cp.async.wait_group 1;" ::: "memory");
            else            asm volatile("cp.async.wait_group 0;" ::: "memory");
            __syncthreads();

            if (s + 2 < NS) {
                const int st2 = (st + 2 >= 3) ? st - 1 : st + 2;
                const uint32_t so = (uint32_t)st2 * STAGE_B;
                const int k0 = (s + 2) * BK;
#pragma unroll
                for (int i = 0; i < 4; i++) {
                    cp16(sa0 + so + (uint32_t)i * 32u * ROWB, Ag + (size_t)(i * 32) * K1 + k0);
                    cp16(sb0 + so + (uint32_t)i * 32u * ROWB, Bg + (size_t)(i * 32) * K1 + k0);
                }
                cp_commit();
            }

            const uint32_t sA = sb + (uint32_t)st * STAGE_B;
            const uint32_t sB = sA + TILE_B;
#pragma unroll
            for (int h = 0; h < 4; h++) {
                const uint32_t ko = (uint32_t)h * 32u;
                uint32_t af[2][4];
#pragma unroll
                for (int mt = 0; mt < 2; mt++) ldsm4(af[mt], sA + aoff[mt] + ko);
                uint32_t bf[4][4];
#pragma unroll
                for (int nb = 0; nb < 4; nb++) ldsm4(bf[nb], sB + boff[nb] + ko);
#pragma unroll
                for (int mt = 0; mt < 2; mt++)
#pragma unroll
                    for (int nt = 0; nt < 8; nt++)
                        mma_f16(acc[mt][nt], af[mt], bf[nt >> 1][(nt & 1) * 2],
                                bf[nt >> 1][(nt & 1) * 2 + 1]);
            }
            st = (st + 1 == 3) ? 0 : st + 1;
        }

#pragma unroll
        for (int nt = 0; nt < 8; nt++) {
            const int col = wn + nt * 8 + 2 * t;
            const float2 bv = *(const float2*)(bp + col);
#pragma unroll
            for (int mt = 0; mt < 2; mt++) {
                const int r = wm + mt * 16 + g;
                float v0 = gelu_erf(acc[mt][nt][0] + bv.x);
                float v1 = gelu_erf(acc[mt][nt][1] + bv.y);
                float v2 = gelu_erf(acc[mt][nt][2] + bv.x);
                float v3 = gelu_erf(acc[mt][nt][3] + bv.y);
                *(__half2*)(outp + (size_t)r * H_DIM + col)       = __floats2half2_rn(v0, v1);
                *(__half2*)(outp + (size_t)(r + 8) * H_DIM + col) = __floats2half2_rn(v2, v3);
            }
        }

        // signal band completion (g_h writes visible before counter bump)
        __threadfence();
        __syncthreads();
        if (tid == 0) atomicAdd(&g_done[bm >> 7], 1);
        return;
    }

    // ================= fc2 side =================
    const int job = b - FC1_CTAS;
    const bool exp_job = (job >= 384);

    int bm, outcol, wm, wn, nAiter;
    bool active;
    const __half* Bb;
    const float* bp;
    if (!exp_job) {
        const int m = job >> 2, n = job & 3;
        bm = m * 128; outcol = n * 128;
        Bb = g_w2 + (size_t)outcol * H_DIM;
        bp = fc2_b + outcol;
        wm = (wid & 3) * 32; wn = (wid >> 2) * 64;
        active = true; nAiter = 4;
    } else {
        const int j = job - 384;               // 0..255
        const int m = j >> 1, nt = j & 1;      // m: 0..127 (M=96 tiles)
        bm = m * 96;
        const int nb = nt * 128;
        wm = 0; wn = 0;                        // set after idx read (needs spin first? g_idx from prep: ready)
        const int e = g_idx[m >> 1];           // prep (prior launch) -> safe
        Bb = g_ew + ((size_t)e * N_PART + nb) * H_DIM;
        bp = eb + (size_t)e * N_PART + nb;
        outcol = N_SHARED + nb;
        active = (wid < 6);
        const int w6 = active ? wid : 0;
        wm = (w6 % 3) * 32; wn = (w6 / 3) * 64;
        nAiter = 3;
    }

    // dependency wait: band(s) of g_h + weight conversion done
    if (tid == 0) {
        const int b0 = bm >> 7;
        const int b1v = (bm + (exp_job ? 95 : 127)) >> 7;
        spin_until(&g_wdone, PREPB_CTAS);
        spin_until(&g_done[b0], 24);
        if (b1v != b0) spin_until(&g_done[b1v], 24);
    }
    __syncthreads();
    __threadfence();   // acquire side: order spins before g_h/g_w2/g_ew reads

    const __half* A = g_h + (size_t)bm * H_DIM;
    const int NS = H_DIM / BK;

    float acc[2][8][4];
#pragma unroll
    for (int mt = 0; mt < 2; mt++)
#pragma unroll
        for (int nt = 0; nt < 8; nt++)
#pragma unroll
            for (int qd = 0; qd < 4; qd++) acc[mt][nt][qd] = 0.f;

    const int r0 = tid >> 3;
    const int c4 = tid & 7;
    const __half* Ag = A + (size_t)r0 * H_DIM + c4 * 8;
    const __half* Bg = Bb + (size_t)r0 * H_DIM + c4 * 8;
    const uint32_t sa0 = sb + (uint32_t)r0 * ROWB + (uint32_t)c4 * 16u;
    const uint32_t sb0 = sa0 + TILE_B;

    const int arow = (lane & 7) + ((lane >> 3) & 1) * 8;
    const int akh  = (lane >> 4);
    uint32_t aoff[2], boff[4];
#pragma unroll
    for (int mt = 0; mt < 2; mt++)
        aoff[mt] = (uint32_t)(wm + mt * 16 + arow) * ROWB + (uint32_t)akh * 16u;
    const int brow = (lane & 7) + ((lane >> 4) & 1) * 8;
    const int bkh  = (lane >> 3) & 1;
#pragma unroll
    for (int nb = 0; nb < 4; nb++)
        boff[nb] = (uint32_t)(wn + nb * 16 + brow) * ROWB + (uint32_t)bkh * 16u;

#pragma unroll
    for (int s = 0; s < 2; s++) {
        const int k0 = s * BK;
        const uint32_t so = (uint32_t)s * STAGE_B;
#pragma unroll
        for (int i = 0; i < 4; i++) {
            if (i < nAiter)
                cp16(sa0 + so + (uint32_t)i * 32u * ROWB, Ag + (size_t)(i * 32) * H_DIM + k0);
            cp16(sb0 + so + (uint32_t)i * 32u * ROWB, Bg + (size_t)(i * 32) * H_DIM + k0);
        }
        cp_commit();
    }

    int st = 0;
    for (int s = 0; s < NS; s++) {
        if (s < NS - 1) asm volatile("cp.async.wait_group 1;" ::: "memory");
        else            asm volatile("cp.async.wait_group 0;" ::: "memory");
        __syncthreads();

        if (s + 2 < NS) {
            const int st2 = (st + 2 >= 3) ? st - 1 : st + 2;
            const uint32_t so = (uint32_t)st2 * STAGE_B;
            const int k0 = (s + 2) * BK;
#pragma unroll
            for (int i = 0; i < 4; i++) {
                if (i < nAiter)
                    cp16(sa0 + so + (uint32_t)i * 32u * ROWB, Ag + (size_t)(i * 32) * H_DIM + k0);
                cp16(sb0 + so + (uint32_t)i * 32u * ROWB, Bg + (size_t)(i * 32) * H_DIM + k0);
            }
            cp_commit();
        }

        if (active) {
            const uint32_t sA = sb + (uint32_t)st * STAGE_B;
            const uint32_t sB = sA + TILE_B;
#pragma unroll
            for (int h = 0; h < 4; h++) {
                const uint32_t ko = (uint32_t)h * 32u;
                uint32_t af[2][4];
#pragma unroll
                for (int mt = 0; mt < 2; mt++) ldsm4(af[mt], sA + aoff[mt] + ko);
                uint32_t bf[4][4];
#pragma unroll
                for (int nb = 0; nb < 4; nb++) ldsm4(bf[nb], sB + boff[nb] + ko);
#pragma unroll
                for (int mt = 0; mt < 2; mt++)
#pragma unroll
                    for (int nt = 0; nt < 8; nt++)
                        mma_f16(acc[mt][nt], af[mt], bf[nt >> 1][(nt & 1) * 2],
                                bf[nt >> 1][(nt & 1) * 2 + 1]);
            }
        }
        st = (st + 1 == 3) ? 0 : st + 1;
    }

    if (active) {
        float* o = out + (size_t)bm * D_OUT + outcol;
#pragma unroll
        for (int nt = 0; nt < 8; nt++) {
            const int col = wn + nt * 8 + 2 * t;
            const float2 bv = *(const float2*)(bp + col);
#pragma unroll
            for (int mt = 0; mt < 2; mt++) {
                const int r = wm + mt * 16 + g;
                float2 v0, v1;
                v0.x = acc[mt][nt][0] + bv.x; v0.y = acc[mt][nt][1] + bv.y;
                v1.x = acc[mt][nt][2] + bv.x; v1.y = acc[mt][nt][3] + bv.y;
                *(float2*)(o + (size_t)r * D_OUT + col) = v0;
                *(float2*)(o + (size_t)(r + 8) * D_OUT + col) = v1;
            }
        }
    }
}

// ---------------- launch ----------------
extern "C" void kernel_launch(void* const* d_in, const int* in_sizes, int n_in,
                              void* d_out, int out_size)
{
    (void)in_sizes; (void)n_in; (void)out_size;
    const float* hs    = (const float*)d_in[0];
    const int*   raw   = (const int*)d_in[1];
    const float* fc1_w = (const float*)d_in[2];
    const float* fc1_b = (const float*)d_in[3];
    const float* fc2_w = (const float*)d_in[4];
    const float* fc2_b = (const float*)d_in[5];
    const float* ew    = (const float*)d_in[6];
    const float* eb    = (const float*)d_in[7];
    float*       out   = (float*)d_out;

    static bool attr_set = false;
    if (!attr_set) {
        cudaFuncSetAttribute(moe_kernel, cudaFuncAttributeMaxDynamicSharedMemorySize, SMEM_BYTES);
        attr_set = true;
    }

    prep_kernel<<<1184, 256>>>(hs, fc1_w, raw);

    // fused: 2378 fc1-side CTAs (low blockIdx) + 640 fc2-side CTAs (high blockIdx)
    moe_kernel<<<FC1_CTAS + FC2_CTAS, 256, SMEM_BYTES>>>(
        fc1_b, fc2_w, ew, fc2_b, eb, out);
}

// round 15
// speedup vs baseline: 1.0320x; 1.0320x over previous
#include <cuda_runtime.h>
#include <cuda_fp16.h>
#include <math.h>
#include <stdint.h>

// ---------------- problem constants ----------------
#define M_TOT   12288
#define K1      768
#define H_DIM   3072
#define N_SHARED 512
#define N_PART  256
#define D_OUT   768
#define S_LEN   192
#define B_TOT   64

#define N_X   ((size_t)M_TOT * K1)
#define N_W1  ((size_t)H_DIM * K1)
#define N_W2  ((size_t)N_SHARED * H_DIM)
#define N_EW  ((size_t)6 * N_PART * H_DIM)

// ---------------- tiling ----------------
#define BK 64                            // halfs of K per stage
#define ROWB 144u                        // smem row pitch bytes (128B data + 16B pad)
#define TILE_B (128u * ROWB)             // 18432 B per operand per stage
#define STAGE_B (2u * TILE_B)            // 36864
#define SMEM_BYTES (3 * 36864)           // 110592 -> 2 CTA/SM

#define PREPB_CTAS 64                    // fc1-embedded w2/ew conversion CTAs
                                         // fc1 grid: 2304+64 = 2368 = 296*8 exact waves

// ---------------- device scratch (fp16 copies) ----------------
static __device__ __half g_h [(size_t)M_TOT * H_DIM];
static __device__ __half g_x [N_X];
static __device__ __half g_w1[N_W1];
static __device__ __half g_w2[N_W2];
static __device__ __half g_ew[N_EW];
static __device__ int    g_idx[B_TOT];

// ---------------- helpers ----------------
__device__ __forceinline__ float gelu_erf(float x) {
    return 0.5f * x * (1.0f + erff(x * 0.70710678118654752440f));
}
__device__ __forceinline__ uint32_t smem_u32(const void* p) {
    uint32_t a;
    asm("{ .reg .u64 t; cvta.to.shared.u64 t, %1; cvt.u32.u64 %0, t; }" : "=r"(a) : "l"(p));
    return a;
}
__device__ __forceinline__ void cp16(uint32_t dst, const __half* src) {
    asm volatile("cp.async.cg.shared.global [%0], [%1], 16;" :: "r"(dst), "l"(src));
}
__device__ __forceinline__ void cp_commit() {
    asm volatile("cp.async.commit_group;" ::: "memory");
}
__device__ __forceinline__ void ldsm4(uint32_t* r, uint32_t addr) {
    asm volatile("ldmatrix.sync.aligned.m8n8.x4.shared.b16 {%0,%1,%2,%3}, [%4];"
                 : "=r"(r[0]), "=r"(r[1]), "=r"(r[2]), "=r"(r[3]) : "r"(addr));
}
__device__ __forceinline__ void mma_f16(float* c, const uint32_t* a, uint32_t b0, uint32_t b1) {
    asm volatile(
        "mma.sync.aligned.m16n8k16.row.col.f32.f16.f16.f32 "
        "{%0,%1,%2,%3}, {%4,%5,%6,%7}, {%8,%9}, {%0,%1,%2,%3};"
        : "+f"(c[0]), "+f"(c[1]), "+f"(c[2]), "+f"(c[3])
        : "r"(a[0]), "r"(a[1]), "r"(a[2]), "r"(a[3]), "r"(b0), "r"(b1));
}

// ---------------- prep: fp32 -> fp16 for X + w1, decode indices ----------------
__global__ void prep_kernel(const float* __restrict__ X,
                            const float* __restrict__ w1,
                            const int*   __restrict__ raw)
{
    if (blockIdx.x == 0 && threadIdx.x == 0) {
        int odd_or = 0;
        for (int i = 1; i < B_TOT; i += 2) odd_or |= raw[i];
        const int is64 = (odd_or == 0);
        for (int b = 0; b < B_TOT; b++) g_idx[b] = is64 ? raw[2 * b] : raw[b];
    }
    const size_t total4 = (N_X + N_W1) / 4;
    const size_t b1 = N_X / 4;
    const size_t stride = (size_t)gridDim.x * blockDim.x;

    auto body = [&](size_t i) {
        const float4* src; __half2* dst; size_t o;
        if (i < b1) { src = (const float4*)X;  dst = (__half2*)g_x;  o = i; }
        else        { src = (const float4*)w1; dst = (__half2*)g_w1; o = i - b1; }
        float4 v = src[o];
        dst[2 * o]     = __floats2half2_rn(v.x, v.y);
        dst[2 * o + 1] = __floats2half2_rn(v.z, v.w);
    };

    size_t i = (size_t)blockIdx.x * blockDim.x + threadIdx.x;
    for (; i + stride < total4; i += 2 * stride) {
        body(i);
        body(i + stride);
    }
    if (i < total4) body(i);
}

// ---------------- kernel 1: g_h = fp16(gelu(X @ fc1_w^T + b)) ----------------
// Grid 2368 (= 296*8, exact waves): 64 scattered prep CTAs (blockIdx%32==31,
// q<64) convert w2/ew; remaining 2304 do the GEMM.
__global__ void __launch_bounds__(256, 2) fc1_kernel(
    const float* __restrict__ bias,
    const float* __restrict__ w2,
    const float* __restrict__ ew)
{
    const int b = blockIdx.x;
    const int q = b >> 5;

    if ((b & 31) == 31 && q < PREPB_CTAS) {
        const size_t nw2 = N_W2 / 4;
        const size_t tot = (N_W2 + N_EW) / 4;
        const size_t stride = (size_t)PREPB_CTAS * 256;
        for (size_t i = (size_t)q * 256 + threadIdx.x; i < tot; i += stride) {
            const float4* src; __half2* dst; size_t o;
            if (i < nw2) { src = (const float4*)w2; dst = (__half2*)g_w2; o = i; }
            else         { src = (const float4*)ew; dst = (__half2*)g_ew; o = i - nw2; }
            float4 v = src[o];
            dst[2 * o]     = __floats2half2_rn(v.x, v.y);
            dst[2 * o + 1] = __floats2half2_rn(v.z, v.w);
        }
        return;
    }

    const int gj = b - ((q < PREPB_CTAS) ? q : PREPB_CTAS);
    const int bm = (gj / 24) * 128;
    const int bn = (gj % 24) * 128;

    const __half* A = g_x + (size_t)bm * K1;
    const __half* B = g_w1 + (size_t)bn * K1;
    __half* out = g_h + (size_t)bm * H_DIM + bn;
    const float* bp = bias + bn;
    const int NS = K1 / BK;

    extern __shared__ char smch[];
    const uint32_t sb = smem_u32(smch);
    const int tid  = threadIdx.x;
    const int lane = tid & 31;
    const int wid  = tid >> 5;
    const int g = lane >> 2;
    const int t = lane & 3;
    const int wm = (wid & 3) * 32;
    const int wn = (wid >> 2) * 64;

    float acc[2][8][4];
#pragma unroll
    for (int mt = 0; mt < 2; mt++)
#pragma unroll
        for (int nt = 0; nt < 8; nt++)
#pragma unroll
            for (int qd = 0; qd < 4; qd++) acc[mt][nt][qd] = 0.f;

    const int r0 = tid >> 3;
    const int c4 = tid & 7;
    const __half* Ag = A + (size_t)r0 * K1 + c4 * 8;
    const __half* Bg = B + (size_t)r0 * K1 + c4 * 8;
    const uint32_t sa0 = sb + (uint32_t)r0 * ROWB + (uint32_t)c4 * 16u;
    const uint32_t sb0 = sa0 + TILE_B;

    const int arow = (lane & 7) + ((lane >> 3) & 1) * 8;
    const int akh  = (lane >> 4);
    uint32_t aoff[2], boff[4];
#pragma unroll
    for (int mt = 0; mt < 2; mt++)
        aoff[mt] = (uint32_t)(wm + mt * 16 + arow) * ROWB + (uint32_t)akh * 16u;
    const int brow = (lane & 7) + ((lane >> 4) & 1) * 8;
    const int bkh  = (lane >> 3) & 1;
#pragma unroll
    for (int nb = 0; nb < 4; nb++)
        boff[nb] = (uint32_t)(wn + nb * 16 + brow) * ROWB + (uint32_t)bkh * 16u;

#pragma unroll
    for (int s = 0; s < 2; s++) {
        const int k0 = s * BK;
        const uint32_t so = (uint32_t)s * STAGE_B;
#pragma unroll
        for (int i = 0; i < 4; i++) {
            cp16(sa0 + so + (uint32_t)i * 32u * ROWB, Ag + (size_t)(i * 32) * K1 + k0);
            cp16(sb0 + so + (uint32_t)i * 32u * ROWB, Bg + (size_t)(i * 32) * K1 + k0);
        }
        cp_commit();
    }

    int st = 0;
    for (int s = 0; s < NS; s++) {
        if (s < NS - 1) asm volatile("cp.async.wait_group 1;" ::: "memory");
        else            asm volatile("cp.async.wait_group 0;" ::: "memory");
        __syncthreads();

        if (s + 2 < NS) {
            const int st2 = (st + 2 >= 3) ? st - 1 : st + 2;
            const uint32_t so = (uint32_t)st2 * STAGE_B;
            const int k0 = (s + 2) * BK;
#pragma unroll
            for (int i = 0; i < 4; i++) {
                cp16(sa0 + so + (uint32_t)i * 32u * ROWB, Ag + (size_t)(i * 32) * K1 + k0);
                cp16(sb0 + so + (uint32_t)i * 32u * ROWB, Bg + (size_t)(i * 32) * K1 + k0);
            }
            cp_commit();
        }

        const uint32_t sA = sb + (uint32_t)st * STAGE_B;
        const uint32_t sB = sA + TILE_B;
#pragma unroll
        for (int h = 0; h < 4; h++) {
            const uint32_t ko = (uint32_t)h * 32u;
            uint32_t af[2][4];
#pragma unroll
            for (int mt = 0; mt < 2; mt++) ldsm4(af[mt], sA + aoff[mt] + ko);
            uint32_t bf[4][4];
#pragma unroll
            for (int nb = 0; nb < 4; nb++) ldsm4(bf[nb], sB + boff[nb] + ko);
#pragma unroll
            for (int mt = 0; mt < 2; mt++)
#pragma unroll
                for (int nt = 0; nt < 8; nt++)
                    mma_f16(acc[mt][nt], af[mt], bf[nt >> 1][(nt & 1) * 2],
                            bf[nt >> 1][(nt & 1) * 2 + 1]);
        }
        st = (st + 1 == 3) ? 0 : st + 1;
    }

#pragma unroll
    for (int nt = 0; nt < 8; nt++) {
        const int col = wn + nt * 8 + 2 * t;
        const float2 bv = *(const float2*)(bp + col);
#pragma unroll
        for (int mt = 0; mt < 2; mt++) {
            const int r = wm + mt * 16 + g;
            float v0 = gelu_erf(acc[mt][nt][0] + bv.x);
            float v1 = gelu_erf(acc[mt][nt][1] + bv.y);
            float v2 = gelu_erf(acc[mt][nt][2] + bv.x);
            float v3 = gelu_erf(acc[mt][nt][3] + bv.y);
            *(__half2*)(out + (size_t)r * H_DIM + col)       = __floats2half2_rn(v0, v1);
            *(__half2*)(out + (size_t)(r + 8) * H_DIM + col) = __floats2half2_rn(v2, v3);
        }
    }
}

// ---------------- kernel 2: fused shared fc2 + expert (R13 proven) ----------------
// jobs 0..383:   shared: M=128 tile, 8 warps 4(M)x2(N)
// jobs 384..639: expert: M=96 tile (192 = 2*96 -> batch-aligned, NO waste),
//                6 compute warps 3(M)x2(N); warps 6-7 idle in MMA, help cp.async.
__global__ void __launch_bounds__(256, 2) fc2_kernel(
    const float* __restrict__ fc2_b,
    const float* __restrict__ eb,
    float* __restrict__ out)
{
    extern __shared__ char smch[];
    const uint32_t sb = smem_u32(smch);
    const int tid  = threadIdx.x;
    const int lane = tid & 31;
    const int wid  = tid >> 5;
    const int g = lane >> 2;
    const int t = lane & 3;

    const int job = blockIdx.x;
    const bool exp_job = (job >= 384);

    int bm, outcol, wm, wn, nAiter;
    bool active;
    const __half* Bb;
    const float* bp;
    if (!exp_job) {
        const int m = job >> 2, n = job & 3;
        bm = m * 128; outcol = n * 128;
        Bb = g_w2 + (size_t)outcol * H_DIM;
        bp = fc2_b + outcol;
        wm = (wid & 3) * 32; wn = (wid >> 2) * 64;
        active = true; nAiter = 4;
    } else {
        const int j = job - 384;               // 0..255
        const int m = j >> 1, nt = j & 1;      // m: 0..127 (M=96 tiles)
        bm = m * 96;
        const int nb = nt * 128;
        const int e = g_idx[m >> 1];           // 192 = 2*96 -> batch = m/2
        Bb = g_ew + ((size_t)e * N_PART + nb) * H_DIM;
        bp = eb + (size_t)e * N_PART + nb;
        outcol = N_SHARED + nb;
        active = (wid < 6);
        const int w6 = active ? wid : 0;
        wm = (w6 % 3) * 32; wn = (w6 / 3) * 64;
        nAiter = 3;
    }
    const __half* A = g_h + (size_t)bm * H_DIM;
    const int NS = H_DIM / BK;

    float acc[2][8][4];
#pragma unroll
    for (int mt = 0; mt < 2; mt++)
#pragma unroll
        for (int nt = 0; nt < 8; nt++)
#pragma unroll
            for (int qd = 0; qd < 4; qd++) acc[mt][nt][qd] = 0.f;

    const int r0 = tid >> 3;
    const int c4 = tid & 7;
    const __half* Ag = A + (size_t)r0 * H_DIM + c4 * 8;
    const __half* Bg = Bb + (size_t)r0 * H_DIM + c4 * 8;
    const uint32_t sa0 = sb + (uint32_t)r0 * ROWB + (uint32_t)c4 * 16u;
    const uint32_t sb0 = sa0 + TILE_B;

    const int arow = (lane & 7) + ((lane >> 3) & 1) * 8;
    const int akh  = (lane >> 4);
    uint32_t aoff[2], boff[4];
#pragma unroll
    for (int mt = 0; mt < 2; mt++)
        aoff[mt] = (uint32_t)(wm + mt * 16 + arow) * ROWB + (uint32_t)akh * 16u;
    const int brow = (lane & 7) + ((lane >> 4) & 1) * 8;
    const int bkh  = (lane >> 3) & 1;
#pragma unroll
    for (int nb = 0; nb < 4; nb++)
        boff[nb] = (uint32_t)(wn + nb * 16 + brow) * ROWB + (uint32_t)bkh * 16u;

#pragma unroll
    for (int s = 0; s < 2; s++) {
        const int k0 = s * BK;
        const uint32_t so = (uint32_t)s * STAGE_B;
#pragma unroll
        for (int i = 0; i < 4; i++) {
            if (i < nAiter)
                cp16(sa0 + so + (uint32_t)i * 32u * ROWB, Ag + (size_t)(i * 32) * H_DIM + k0);
            cp16(sb0 + so + (uint32_t)i * 32u * ROWB, Bg + (size_t)(i * 32) * H_DIM + k0);
        }
        cp_commit();
    }

    int st = 0;
    for (int s = 0; s < NS; s++) {
        if (s < NS - 1) asm volatile("cp.async.wait_group 1;" ::: "memory");
        else            asm volatile("cp.async.wait_group 0;" ::: "memory");
        __syncthreads();

        if (s + 2 < NS) {
            const int st2 = (st + 2 >= 3) ? st - 1 : st + 2;
            const uint32_t so = (uint32_t)st2 * STAGE_B;
            const int k0 = (s + 2) * BK;
#pragma unroll
            for (int i = 0; i < 4; i++) {
                if (i < nAiter)
                    cp16(sa0 + so + (uint32_t)i * 32u * ROWB, Ag + (size_t)(i * 32) * H_DIM + k0);
                cp16(sb0 + so + (uint32_t)i * 32u * ROWB, Bg + (size_t)(i * 32) * H_DIM + k0);
            }
            cp_commit();
        }

        if (active) {
            const uint32_t sA = sb + (uint32_t)st * STAGE_B;
            const uint32_t sB = sA + TILE_B;
#pragma unroll
            for (int h = 0; h < 4; h++) {
                const uint32_t ko = (uint32_t)h * 32u;
                uint32_t af[2][4];
#pragma unroll
                for (int mt = 0; mt < 2; mt++) ldsm4(af[mt], sA + aoff[mt] + ko);
                uint32_t bf[4][4];
#pragma unroll
                for (int nb = 0; nb < 4; nb++) ldsm4(bf[nb], sB + boff[nb] + ko);
#pragma unroll
                for (int mt = 0; mt < 2; mt++)
#pragma unroll
                    for (int nt = 0; nt < 8; nt++)
                        mma_f16(acc[mt][nt], af[mt], bf[nt >> 1][(nt & 1) * 2],
                                bf[nt >> 1][(nt & 1) * 2 + 1]);
            }
        }
        st = (st + 1 == 3) ? 0 : st + 1;
    }

    if (active) {
        float* o = out + (size_t)bm * D_OUT + outcol;
#pragma unroll
        for (int nt = 0; nt < 8; nt++) {
            const int col = wn + nt * 8 + 2 * t;
            const float2 bv = *(const float2*)(bp + col);
#pragma unroll
            for (int mt = 0; mt < 2; mt++) {
                const int r = wm + mt * 16 + g;
                float2 v0, v1;
                v0.x = acc[mt][nt][0] + bv.x; v0.y = acc[mt][nt][1] + bv.y;
                v1.x = acc[mt][nt][2] + bv.x; v1.y = acc[mt][nt][3] + bv.y;
                *(float2*)(o + (size_t)r * D_OUT + col) = v0;
                *(float2*)(o + (size_t)(r + 8) * D_OUT + col) = v1;
            }
        }
    }
}

// ---------------- launch ----------------
extern "C" void kernel_launch(void* const* d_in, const int* in_sizes, int n_in,
                              void* d_out, int out_size)
{
    (void)in_sizes; (void)n_in; (void)out_size;
    const float* hs    = (const float*)d_in[0];
    const int*   raw   = (const int*)d_in[1];
    const float* fc1_w = (const float*)d_in[2];
    const float* fc1_b = (const float*)d_in[3];
    const float* fc2_w = (const float*)d_in[4];
    const float* fc2_b = (const float*)d_in[5];
    const float* ew    = (const float*)d_in[6];
    const float* eb    = (const float*)d_in[7];
    float*       out   = (float*)d_out;

    static bool attr_set = false;
    if (!attr_set) {
        cudaFuncSetAttribute(fc1_kernel, cudaFuncAttributeMaxDynamicSharedMemorySize, SMEM_BYTES);
        cudaFuncSetAttribute(fc2_kernel, cudaFuncAttributeMaxDynamicSharedMemorySize, SMEM_BYTES);
        attr_set = true;
    }

    prep_kernel<<<1184, 256>>>(hs, fc1_w, raw);

    // 2304 GEMM CTAs + 64 scattered prep-B CTAs = 2368 = 8 exact waves
    fc1_kernel<<<2304 + PREPB_CTAS, 256, SMEM_BYTES>>>(fc1_b, fc2_w, ew);

    // 384 shared (M=128) + 256 expert (M=96) jobs
    fc2_kernel<<<640, 256, SMEM_BYTES>>>(fc2_b, eb, out);
}